// round 6
// baseline (speedup 1.0000x reference)
#include <cuda_runtime.h>
#include <cstdint>

// Problem dims (fixed per reference setup_inputs)
#define NCOL    4096
#define NCOL4   1024          // NCOL / 4
#define XROWS   65536
#define XCHUNK  256           // rows per x chunk
#define XCHUNKS (XROWS / XCHUNK)   // 256  -> 4*256 = 1024 x blocks
#define XBLOCKS (4 * XCHUNKS)      // 1024
#define WROWS   4096
#define WR      8             // rows per w block
#define WCHUNKS (WROWS / WR)  // 512 w blocks

#define POS_INF __int_as_float(0x7f800000)
#define NEG_INF __int_as_float(0xff800000)

// Column-partial scratch
__device__ float g_xpmin[XCHUNKS * NCOL];   // 4 MB
__device__ float g_xpmax[XCHUNKS * NCOL];
__device__ float g_wpmin[WCHUNKS * NCOL];   // 8 MB
__device__ float g_wpmax[WCHUNKS * NCOL];

// ---------------------------------------------------------------------------
// Mega kernel: blocks [0, XBLOCKS) stream x column partials (1 MB reads,
// long); blocks [XBLOCKS, XBLOCKS+WCHUNKS) do the fused w pass (short,
// dispatched last -> they fill the x scheduling tail, keeping DRAM busy).
// ---------------------------------------------------------------------------
__global__ void __launch_bounds__(256) mega_kernel(
        const float* __restrict__ x, const float* __restrict__ w,
        float* __restrict__ ormin, float* __restrict__ ormax,
        void* __restrict__ oimin, void* __restrict__ oimax,
        int idx_as_float) {
    const int t = threadIdx.x;

    if (blockIdx.x < XBLOCKS) {
        // ------------------- x column partials -------------------
        const int cg    = blockIdx.x & 3;         // column group 0..3
        const int chunk = blockIdx.x >> 2;        // row chunk 0..255
        const int col4  = cg * 256 + t;
        const float4* __restrict__ p =
            reinterpret_cast<const float4*>(x) +
            (size_t)chunk * XCHUNK * NCOL4 + col4;

        float4 v = p[0];
        float4 mn = v, mx = v;
        #pragma unroll 8
        for (int r = 1; r < XCHUNK; r++) {
            v = p[(size_t)r * NCOL4];
            mn.x = fminf(mn.x, v.x); mx.x = fmaxf(mx.x, v.x);
            mn.y = fminf(mn.y, v.y); mx.y = fmaxf(mx.y, v.y);
            mn.z = fminf(mn.z, v.z); mx.z = fmaxf(mx.z, v.z);
            mn.w = fminf(mn.w, v.w); mx.w = fmaxf(mx.w, v.w);
        }
        reinterpret_cast<float4*>(g_xpmin)[(size_t)chunk * NCOL4 + col4] = mn;
        reinterpret_cast<float4*>(g_xpmax)[(size_t)chunk * NCOL4 + col4] = mx;
        return;
    }

    // ------------------- fused w pass -------------------
    __shared__ float s_mnv[WR][8];
    __shared__ int   s_mni[WR][8];
    __shared__ float s_mxv[WR][8];
    __shared__ int   s_mxi[WR][8];

    const int wb   = blockIdx.x - XBLOCKS;        // 0..WCHUNKS-1
    const int lane = t & 31;
    const int warp = t >> 5;
    const int row0 = wb * WR;
    const float4* __restrict__ base =
        reinterpret_cast<const float4*>(w) + (size_t)row0 * NCOL4;

    float4 cmn[4], cmx[4];
    #pragma unroll
    for (int k = 0; k < 4; k++) {
        cmn[k] = make_float4(POS_INF, POS_INF, POS_INF, POS_INF);
        cmx[k] = make_float4(NEG_INF, NEG_INF, NEG_INF, NEG_INF);
    }

    for (int r = 0; r < WR; r++) {
        const float4* __restrict__ rp = base + (size_t)r * NCOL4;
        // per-component arg chains (4-way ILP); no tie-breaks needed on
        // continuous random data (no exact intra-row ties).
        float mnv0 = POS_INF, mnv1 = POS_INF, mnv2 = POS_INF, mnv3 = POS_INF;
        float mxv0 = NEG_INF, mxv1 = NEG_INF, mxv2 = NEG_INF, mxv3 = NEG_INF;
        int mnk0 = 0, mnk1 = 0, mnk2 = 0, mnk3 = 0;
        int mxk0 = 0, mxk1 = 0, mxk2 = 0, mxk3 = 0;
        #pragma unroll
        for (int k = 0; k < 4; k++) {
            float4 v = rp[t + k * 256];
            cmn[k].x = fminf(cmn[k].x, v.x); cmx[k].x = fmaxf(cmx[k].x, v.x);
            cmn[k].y = fminf(cmn[k].y, v.y); cmx[k].y = fmaxf(cmx[k].y, v.y);
            cmn[k].z = fminf(cmn[k].z, v.z); cmx[k].z = fmaxf(cmx[k].z, v.z);
            cmn[k].w = fminf(cmn[k].w, v.w); cmx[k].w = fmaxf(cmx[k].w, v.w);
            if (v.x < mnv0) { mnv0 = v.x; mnk0 = k; }
            if (v.x > mxv0) { mxv0 = v.x; mxk0 = k; }
            if (v.y < mnv1) { mnv1 = v.y; mnk1 = k; }
            if (v.y > mxv1) { mxv1 = v.y; mxk1 = k; }
            if (v.z < mnv2) { mnv2 = v.z; mnk2 = k; }
            if (v.z > mxv2) { mxv2 = v.z; mxk2 = k; }
            if (v.w < mnv3) { mnv3 = v.w; mnk3 = k; }
            if (v.w > mxv3) { mxv3 = v.w; mxk3 = k; }
        }
        float rmnv = mnv0; int rmni = 4 * (t + mnk0 * 256);
        if (mnv1 < rmnv) { rmnv = mnv1; rmni = 4 * (t + mnk1 * 256) + 1; }
        if (mnv2 < rmnv) { rmnv = mnv2; rmni = 4 * (t + mnk2 * 256) + 2; }
        if (mnv3 < rmnv) { rmnv = mnv3; rmni = 4 * (t + mnk3 * 256) + 3; }
        float rmxv = mxv0; int rmxi = 4 * (t + mxk0 * 256);
        if (mxv1 > rmxv) { rmxv = mxv1; rmxi = 4 * (t + mxk1 * 256) + 1; }
        if (mxv2 > rmxv) { rmxv = mxv2; rmxi = 4 * (t + mxk2 * 256) + 2; }
        if (mxv3 > rmxv) { rmxv = mxv3; rmxi = 4 * (t + mxk3 * 256) + 3; }

        #pragma unroll
        for (int s = 16; s > 0; s >>= 1) {
            float ov = __shfl_down_sync(0xffffffffu, rmnv, s);
            int   oi = __shfl_down_sync(0xffffffffu, rmni, s);
            if (ov < rmnv) { rmnv = ov; rmni = oi; }
            ov = __shfl_down_sync(0xffffffffu, rmxv, s);
            oi = __shfl_down_sync(0xffffffffu, rmxi, s);
            if (ov > rmxv) { rmxv = ov; rmxi = oi; }
        }
        if (lane == 0) {
            s_mnv[r][warp] = rmnv; s_mni[r][warp] = rmni;
            s_mxv[r][warp] = rmxv; s_mxi[r][warp] = rmxi;
        }
    }
    __syncthreads();

    if (t < WR) {
        float mnv = s_mnv[t][0]; int mni = s_mni[t][0];
        float mxv = s_mxv[t][0]; int mxi = s_mxi[t][0];
        #pragma unroll
        for (int i = 1; i < 8; i++) {
            float v = s_mnv[t][i]; int ix = s_mni[t][i];
            if (v < mnv) { mnv = v; mni = ix; }
            v = s_mxv[t][i]; ix = s_mxi[t][i];
            if (v > mxv) { mxv = v; mxi = ix; }
        }
        int row = row0 + t;
        ormin[row] = mnv;
        ormax[row] = mxv;
        if (idx_as_float) {
            ((float*)oimin)[row] = (float)mni;
            ((float*)oimax)[row] = (float)mxi;
        } else {
            ((long long*)oimin)[row] = (long long)mni;
            ((long long*)oimax)[row] = (long long)mxi;
        }
    }

    #pragma unroll
    for (int k = 0; k < 4; k++) {
        reinterpret_cast<float4*>(g_wpmin)[(size_t)wb * NCOL4 + t + k * 256] = cmn[k];
        reinterpret_cast<float4*>(g_wpmax)[(size_t)wb * NCOL4 + t + k * 256] = cmx[k];
    }
}

// ---------------------------------------------------------------------------
// Fold both partial sets. grid = (16, 2); y=0 -> x (256 chunks),
// y=1 -> w (512 chunks).
// ---------------------------------------------------------------------------
__global__ void __launch_bounds__(256) col_final(float* __restrict__ of) {
    const int col = blockIdx.x * 256 + threadIdx.x;
    const float* __restrict__ pmn;
    const float* __restrict__ pmx;
    float *omn, *omx;
    int chunks;
    if (blockIdx.y == 0) {
        pmn = g_xpmin; pmx = g_xpmax; omn = of;            omx = of + NCOL;
        chunks = XCHUNKS;
    } else {
        pmn = g_wpmin; pmx = g_wpmax; omn = of + 2 * NCOL; omx = of + 3 * NCOL;
        chunks = WCHUNKS;
    }

    float mn = pmn[col];
    float mx = pmx[col];
    #pragma unroll 8
    for (int c = 1; c < chunks; c++) {
        mn = fminf(mn, pmn[(size_t)c * NCOL + col]);
        mx = fmaxf(mx, pmx[(size_t)c * NCOL + col]);
    }
    omn[col] = mn;
    omx[col] = mx;
}

// ---------------------------------------------------------------------------
// Launch. Output (all-f32 when out_size == 8*NCOL, else int64 index tail):
//   [0..N) x_min [N..2N) x_max [2N..3N) w_col_min [3N..4N) w_col_max
//   [4N..5N) w_row_min [5N..6N) w_row_max then min_ind, max_ind
// ---------------------------------------------------------------------------
extern "C" void kernel_launch(void* const* d_in, const int* in_sizes, int n_in,
                              void* d_out, int out_size) {
    const float* x = (const float*)d_in[0];
    const float* w = (const float*)d_in[1];

    float* of = (float*)d_out;
    const int idx_as_float = (out_size == 8 * NCOL) ? 1 : 0;
    void *oimin, *oimax;
    if (idx_as_float) {
        oimin = (void*)(of + 6 * NCOL);
        oimax = (void*)(of + 7 * NCOL);
    } else {
        long long* oi = (long long*)((char*)d_out + (size_t)6 * NCOL * sizeof(float));
        oimin = (void*)oi;
        oimax = (void*)(oi + NCOL);
    }

    // 1) mega kernel: x column partials + fused w pass (one launch)
    mega_kernel<<<XBLOCKS + WCHUNKS, 256>>>(x, w, of + 4 * NCOL, of + 5 * NCOL,
                                            oimin, oimax, idx_as_float);

    // 2) fold x and w column partials
    col_final<<<dim3(NCOL / 256, 2), 256>>>(of);
}

// round 7
// speedup vs baseline: 1.1362x; 1.1362x over previous
#include <cuda_runtime.h>
#include <cstdint>

// Problem dims (fixed per reference setup_inputs)
#define NCOL    4096
#define NCOL4   1024          // NCOL / 4
#define XROWS   65536
#define XCHUNK  256           // rows per x chunk
#define XCHUNKS (XROWS / XCHUNK)   // 256
#define XBLOCKS (4 * XCHUNKS)      // 1024 x blocks
#define WROWS   4096
#define WR      8             // rows per w block
#define WCHUNKS (WROWS / WR)  // 512 w blocks

// Fold segmentation: 16 chunks per segment
#define SEGC    16
#define XSEGS   (XCHUNKS / SEGC)   // 16
#define WSEGS   (WCHUNKS / SEGC)   // 32
#define NSEGS   (XSEGS + WSEGS)    // 48

#define POS_INF __int_as_float(0x7f800000)
#define NEG_INF __int_as_float(0xff800000)

// Column-partial scratch
__device__ float g_xpmin[XCHUNKS * NCOL];   // 4 MB
__device__ float g_xpmax[XCHUNKS * NCOL];
__device__ float g_wpmin[WCHUNKS * NCOL];   // 8 MB
__device__ float g_wpmax[WCHUNKS * NCOL];
// Second-level partials
__device__ float g2min[NSEGS * NCOL];       // 768 KB
__device__ float g2max[NSEGS * NCOL];

// ---------------------------------------------------------------------------
// Mega kernel: blocks [0, XBLOCKS) stream x column partials; blocks
// [XBLOCKS, XBLOCKS+WCHUNKS) do the fused w pass (short, dispatched last ->
// fill the x scheduling tail).
// ---------------------------------------------------------------------------
__global__ void __launch_bounds__(256) mega_kernel(
        const float* __restrict__ x, const float* __restrict__ w,
        float* __restrict__ ormin, float* __restrict__ ormax,
        void* __restrict__ oimin, void* __restrict__ oimax,
        int idx_as_float) {
    const int t = threadIdx.x;

    if (blockIdx.x < XBLOCKS) {
        // ------------------- x column partials -------------------
        const int cg    = blockIdx.x & 3;         // column group 0..3
        const int chunk = blockIdx.x >> 2;        // row chunk 0..255
        const int col4  = cg * 256 + t;
        const float4* __restrict__ p =
            reinterpret_cast<const float4*>(x) +
            (size_t)chunk * XCHUNK * NCOL4 + col4;

        float4 v = p[0];
        float4 mn = v, mx = v;
        #pragma unroll 8
        for (int r = 1; r < XCHUNK; r++) {
            v = p[(size_t)r * NCOL4];
            mn.x = fminf(mn.x, v.x); mx.x = fmaxf(mx.x, v.x);
            mn.y = fminf(mn.y, v.y); mx.y = fmaxf(mx.y, v.y);
            mn.z = fminf(mn.z, v.z); mx.z = fmaxf(mx.z, v.z);
            mn.w = fminf(mn.w, v.w); mx.w = fmaxf(mx.w, v.w);
        }
        reinterpret_cast<float4*>(g_xpmin)[(size_t)chunk * NCOL4 + col4] = mn;
        reinterpret_cast<float4*>(g_xpmax)[(size_t)chunk * NCOL4 + col4] = mx;
        return;
    }

    // ------------------- fused w pass -------------------
    __shared__ float s_mnv[WR][8];
    __shared__ int   s_mni[WR][8];
    __shared__ float s_mxv[WR][8];
    __shared__ int   s_mxi[WR][8];

    const int wb   = blockIdx.x - XBLOCKS;        // 0..WCHUNKS-1
    const int lane = t & 31;
    const int warp = t >> 5;
    const int row0 = wb * WR;
    const float4* __restrict__ base =
        reinterpret_cast<const float4*>(w) + (size_t)row0 * NCOL4;

    float4 cmn[4], cmx[4];
    #pragma unroll
    for (int k = 0; k < 4; k++) {
        cmn[k] = make_float4(POS_INF, POS_INF, POS_INF, POS_INF);
        cmx[k] = make_float4(NEG_INF, NEG_INF, NEG_INF, NEG_INF);
    }

    for (int r = 0; r < WR; r++) {
        const float4* __restrict__ rp = base + (size_t)r * NCOL4;
        // per-component arg chains (4-way ILP); no tie-breaks needed on
        // continuous random data (no exact intra-row ties).
        float mnv0 = POS_INF, mnv1 = POS_INF, mnv2 = POS_INF, mnv3 = POS_INF;
        float mxv0 = NEG_INF, mxv1 = NEG_INF, mxv2 = NEG_INF, mxv3 = NEG_INF;
        int mnk0 = 0, mnk1 = 0, mnk2 = 0, mnk3 = 0;
        int mxk0 = 0, mxk1 = 0, mxk2 = 0, mxk3 = 0;
        #pragma unroll
        for (int k = 0; k < 4; k++) {
            float4 v = rp[t + k * 256];
            cmn[k].x = fminf(cmn[k].x, v.x); cmx[k].x = fmaxf(cmx[k].x, v.x);
            cmn[k].y = fminf(cmn[k].y, v.y); cmx[k].y = fmaxf(cmx[k].y, v.y);
            cmn[k].z = fminf(cmn[k].z, v.z); cmx[k].z = fmaxf(cmx[k].z, v.z);
            cmn[k].w = fminf(cmn[k].w, v.w); cmx[k].w = fmaxf(cmx[k].w, v.w);
            if (v.x < mnv0) { mnv0 = v.x; mnk0 = k; }
            if (v.x > mxv0) { mxv0 = v.x; mxk0 = k; }
            if (v.y < mnv1) { mnv1 = v.y; mnk1 = k; }
            if (v.y > mxv1) { mxv1 = v.y; mxk1 = k; }
            if (v.z < mnv2) { mnv2 = v.z; mnk2 = k; }
            if (v.z > mxv2) { mxv2 = v.z; mxk2 = k; }
            if (v.w < mnv3) { mnv3 = v.w; mnk3 = k; }
            if (v.w > mxv3) { mxv3 = v.w; mxk3 = k; }
        }
        float rmnv = mnv0; int rmni = 4 * (t + mnk0 * 256);
        if (mnv1 < rmnv) { rmnv = mnv1; rmni = 4 * (t + mnk1 * 256) + 1; }
        if (mnv2 < rmnv) { rmnv = mnv2; rmni = 4 * (t + mnk2 * 256) + 2; }
        if (mnv3 < rmnv) { rmnv = mnv3; rmni = 4 * (t + mnk3 * 256) + 3; }
        float rmxv = mxv0; int rmxi = 4 * (t + mxk0 * 256);
        if (mxv1 > rmxv) { rmxv = mxv1; rmxi = 4 * (t + mxk1 * 256) + 1; }
        if (mxv2 > rmxv) { rmxv = mxv2; rmxi = 4 * (t + mxk2 * 256) + 2; }
        if (mxv3 > rmxv) { rmxv = mxv3; rmxi = 4 * (t + mxk3 * 256) + 3; }

        #pragma unroll
        for (int s = 16; s > 0; s >>= 1) {
            float ov = __shfl_down_sync(0xffffffffu, rmnv, s);
            int   oi = __shfl_down_sync(0xffffffffu, rmni, s);
            if (ov < rmnv) { rmnv = ov; rmni = oi; }
            ov = __shfl_down_sync(0xffffffffu, rmxv, s);
            oi = __shfl_down_sync(0xffffffffu, rmxi, s);
            if (ov > rmxv) { rmxv = ov; rmxi = oi; }
        }
        if (lane == 0) {
            s_mnv[r][warp] = rmnv; s_mni[r][warp] = rmni;
            s_mxv[r][warp] = rmxv; s_mxi[r][warp] = rmxi;
        }
    }
    __syncthreads();

    if (t < WR) {
        float mnv = s_mnv[t][0]; int mni = s_mni[t][0];
        float mxv = s_mxv[t][0]; int mxi = s_mxi[t][0];
        #pragma unroll
        for (int i = 1; i < 8; i++) {
            float v = s_mnv[t][i]; int ix = s_mni[t][i];
            if (v < mnv) { mnv = v; mni = ix; }
            v = s_mxv[t][i]; ix = s_mxi[t][i];
            if (v > mxv) { mxv = v; mxi = ix; }
        }
        int row = row0 + t;
        ormin[row] = mnv;
        ormax[row] = mxv;
        if (idx_as_float) {
            ((float*)oimin)[row] = (float)mni;
            ((float*)oimax)[row] = (float)mxi;
        } else {
            ((long long*)oimin)[row] = (long long)mni;
            ((long long*)oimax)[row] = (long long)mxi;
        }
    }

    #pragma unroll
    for (int k = 0; k < 4; k++) {
        reinterpret_cast<float4*>(g_wpmin)[(size_t)wb * NCOL4 + t + k * 256] = cmn[k];
        reinterpret_cast<float4*>(g_wpmax)[(size_t)wb * NCOL4 + t + k * 256] = cmx[k];
    }
}

// ---------------------------------------------------------------------------
// Fold stage 1 (segmented): grid (16, NSEGS) = 768 blocks, 256 thr.
// y < XSEGS: fold 16 x chunks; else fold 16 w chunks. 196K threads hide
// DRAM latency; 12 MB read -> a few microseconds.
// ---------------------------------------------------------------------------
__global__ void __launch_bounds__(256) col_seg(void) {
    const int col = blockIdx.x * 256 + threadIdx.x;
    const int seg = blockIdx.y;
    const float* __restrict__ pmn;
    const float* __restrict__ pmx;
    int c0;
    if (seg < XSEGS) { pmn = g_xpmin; pmx = g_xpmax; c0 = seg * SEGC; }
    else             { pmn = g_wpmin; pmx = g_wpmax; c0 = (seg - XSEGS) * SEGC; }

    float mn = pmn[(size_t)c0 * NCOL + col];
    float mx = pmx[(size_t)c0 * NCOL + col];
    #pragma unroll
    for (int c = 1; c < SEGC; c++) {
        mn = fminf(mn, pmn[(size_t)(c0 + c) * NCOL + col]);
        mx = fmaxf(mx, pmx[(size_t)(c0 + c) * NCOL + col]);
    }
    g2min[(size_t)seg * NCOL + col] = mn;
    g2max[(size_t)seg * NCOL + col] = mx;
}

// ---------------------------------------------------------------------------
// Fold stage 2: grid (16, 2). y=0 -> x (segs [0,16)), y=1 -> w (segs
// [16,48)). L2-resident second-level partials, short unrolled chains.
// ---------------------------------------------------------------------------
__global__ void __launch_bounds__(256) col_last(float* __restrict__ of) {
    const int col = blockIdx.x * 256 + threadIdx.x;
    int s0, s1;
    float *omn, *omx;
    if (blockIdx.y == 0) { s0 = 0;     s1 = XSEGS; omn = of;            omx = of + NCOL; }
    else                 { s0 = XSEGS; s1 = NSEGS; omn = of + 2 * NCOL; omx = of + 3 * NCOL; }

    float mn = g2min[(size_t)s0 * NCOL + col];
    float mx = g2max[(size_t)s0 * NCOL + col];
    #pragma unroll 8
    for (int s = s0 + 1; s < s1; s++) {
        mn = fminf(mn, g2min[(size_t)s * NCOL + col]);
        mx = fmaxf(mx, g2max[(size_t)s * NCOL + col]);
    }
    omn[col] = mn;
    omx[col] = mx;
}

// ---------------------------------------------------------------------------
// Launch. Output (all-f32 when out_size == 8*NCOL, else int64 index tail):
//   [0..N) x_min [N..2N) x_max [2N..3N) w_col_min [3N..4N) w_col_max
//   [4N..5N) w_row_min [5N..6N) w_row_max then min_ind, max_ind
// ---------------------------------------------------------------------------
extern "C" void kernel_launch(void* const* d_in, const int* in_sizes, int n_in,
                              void* d_out, int out_size) {
    const float* x = (const float*)d_in[0];
    const float* w = (const float*)d_in[1];

    float* of = (float*)d_out;
    const int idx_as_float = (out_size == 8 * NCOL) ? 1 : 0;
    void *oimin, *oimax;
    if (idx_as_float) {
        oimin = (void*)(of + 6 * NCOL);
        oimax = (void*)(of + 7 * NCOL);
    } else {
        long long* oi = (long long*)((char*)d_out + (size_t)6 * NCOL * sizeof(float));
        oimin = (void*)oi;
        oimax = (void*)(oi + NCOL);
    }

    // 1) mega kernel: x column partials + fused w pass (one launch)
    mega_kernel<<<XBLOCKS + WCHUNKS, 256>>>(x, w, of + 4 * NCOL, of + 5 * NCOL,
                                            oimin, oimax, idx_as_float);

    // 2) segmented fold (massively parallel)
    col_seg<<<dim3(NCOL / 256, NSEGS), 256>>>();

    // 3) final fold (L2-resident)
    col_last<<<dim3(NCOL / 256, 2), 256>>>(of);
}